// round 10
// baseline (speedup 1.0000x reference)
#include <cuda_runtime.h>
#include <cuda_bf16.h>
#include <cstdint>

#define NN   100000
#define EE   1000000
#define DIN  64
#define DH   128
#define DOUT 64
#define NB_SCAN 391                     // ceil(NN/256)
#define NT1 ((NN + 31) / 32)            // layer1 tiles of 32 nodes
#define NTH ((NN + 63) / 64)            // hmul tiles of 64 nodes

typedef unsigned long long ull;

// ----- device scratch (no allocation allowed) -----
__device__ int    g_is64;
__device__ int    g_cnti[NN];
__device__ int    g_bsum[NB_SCAN];
__device__ int    g_off[NN + 1];
__device__ int    g_cur[NN];
__device__ float  g_inv[NN];
__device__ int    g_src[EE];
__device__ int    g_dst[EE];
__device__ int    g_esrc[EE];                      // src sorted by dst bucket
__device__ float4 g_mean1[(size_t)NN * (DIN / 4)];
__device__ float4 g_h4[(size_t)NN * (DH / 4)];
__device__ float4 g_y[(size_t)NN * (DOUT / 4)];

// ---- packed f32x2 helpers (Blackwell FFMA2 — ptxas never emits from C++) ----
__device__ __forceinline__ ull pk2(float a, float b) {
    ull r; asm("mov.b64 %0, {%1, %2};" : "=l"(r) : "f"(a), "f"(b)); return r;
}
__device__ __forceinline__ void upk2(float& a, float& b, ull v) {
    asm("mov.b64 {%0, %1}, %2;" : "=f"(a), "=f"(b) : "l"(v));
}
__device__ __forceinline__ void fma2(ull& d, ull a, ull b) {
    asm("fma.rn.f32x2 %0, %1, %2, %0;" : "+l"(d) : "l"(a), "l"(b));
}

// ------------------- detect edge_index storage width + zero degree histogram
__global__ void detect_zero_kernel(const int* __restrict__ ei) {
    int i = blockIdx.x * blockDim.x + threadIdx.x;
    if (i < NN) g_cnti[i] = 0;
    if (blockIdx.x == 0) {
        __shared__ int any_nonzero;
        if (threadIdx.x == 0) any_nonzero = 0;
        __syncthreads();
        int w = 1 + 2 * threadIdx.x;            // odd words 1..2047
        if (w < 2048 && ei[w] != 0) atomicExch(&any_nonzero, 1);
        __syncthreads();
        if (threadIdx.x == 0) g_is64 = any_nonzero ? 0 : 1;
    }
}

// --------------------------------- convert indices to int32 + degree histogram
__global__ void convert_kernel(const int* __restrict__ ei) {
    int e = blockIdx.x * blockDim.x + threadIdx.x;
    if (e >= EE) return;
    int is64 = g_is64;
    int s = is64 ? ei[2 * e] : ei[e];
    int d = is64 ? ei[2 * (EE + e)] : ei[EE + e];
    s = min(max(s, 0), NN - 1);
    d = min(max(d, 0), NN - 1);
    g_src[e] = s;
    g_dst[e] = d;
    atomicAdd(&g_cnti[d], 1);
}

// ------------------------------------------------------- 2-phase scan
__global__ void scan1_kernel() {
    __shared__ int s[256];
    int i = blockIdx.x * 256 + threadIdx.x;
    s[threadIdx.x] = (i < NN) ? g_cnti[i] : 0;
    __syncthreads();
    for (int d = 128; d > 0; d >>= 1) {
        if (threadIdx.x < d) s[threadIdx.x] += s[threadIdx.x + d];
        __syncthreads();
    }
    if (threadIdx.x == 0) g_bsum[blockIdx.x] = s[0];
}

// scan3: per-element offsets; block offset computed by reducing g_bsum[0..b)
__global__ void scan3_kernel() {
    __shared__ int s[256];
    __shared__ int sboff[256];
    int t = threadIdx.x;
    // block-prefix: sum of g_bsum[0 .. blockIdx.x)
    int part = 0;
    for (int k = t; k < blockIdx.x; k += 256) part += g_bsum[k];
    sboff[t] = part;
    __syncthreads();
    for (int d = 128; d > 0; d >>= 1) {
        if (t < d) sboff[t] += sboff[t + d];
        __syncthreads();
    }
    int block_off = sboff[0];

    int i = blockIdx.x * 256 + t;
    int c = (i < NN) ? g_cnti[i] : 0;
    s[t] = c;
    __syncthreads();
    for (int d = 1; d < 256; d <<= 1) {
        int v = (t >= d) ? s[t - d] : 0;
        __syncthreads();
        s[t] += v;
        __syncthreads();
    }
    if (i < NN) {
        int off = block_off + s[t] - c;
        g_off[i] = off;
        g_cur[i] = off;
        g_inv[i] = 1.0f / fmaxf((float)c, 1.0f);
    }
    if (i == 0) g_off[NN] = EE;
}

// -------------------------------------------------- bucket-place src by dst
__global__ void place_kernel() {
    int e = blockIdx.x * blockDim.x + threadIdx.x;
    if (e >= EE) return;
    int pos = atomicAdd(&g_cur[g_dst[e]], 1);
    g_esrc[pos] = g_src[e];
}

// ----------------------------------- gather-aggregate: mean1 = mean x[nbrs]
__global__ void __launch_bounds__(256)
agg1_kernel(const float* __restrict__ x) {
    int gwarp = (blockIdx.x * 256 + threadIdx.x) >> 5;
    int lane = threadIdx.x & 31;
    int nw = (gridDim.x * 256) >> 5;
    int chunk = lane & 15, par = lane >> 4;
    const float4* x4 = (const float4*)x;
    for (int node = gwarp; node < NN; node += nw) {
        int s = g_off[node], e = g_off[node + 1];
        float4 acc = make_float4(0.f, 0.f, 0.f, 0.f);
        for (int i = s + par; i < e; i += 2) {
            int src = g_esrc[i];
            float4 v = x4[(size_t)src * 16 + chunk];
            acc.x += v.x; acc.y += v.y; acc.z += v.z; acc.w += v.w;
        }
        acc.x += __shfl_down_sync(0xffffffffu, acc.x, 16);
        acc.y += __shfl_down_sync(0xffffffffu, acc.y, 16);
        acc.z += __shfl_down_sync(0xffffffffu, acc.z, 16);
        acc.w += __shfl_down_sync(0xffffffffu, acc.w, 16);
        if (par == 0) {
            float inv = g_inv[node];
            g_mean1[(size_t)node * 16 + chunk] =
                make_float4(acc.x * inv, acc.y * inv, acc.z * inv, acc.w * inv);
        }
    }
}

// --------------- gather-aggregate 2 FUSED: out += mean y[nbrs] + b2
__global__ void __launch_bounds__(256)
agg2_kernel(const float* __restrict__ b2, float* __restrict__ out) {
    int gwarp = (blockIdx.x * 256 + threadIdx.x) >> 5;
    int lane = threadIdx.x & 31;
    int nw = (gridDim.x * 256) >> 5;
    int chunk = lane & 15, par = lane >> 4;
    float4* out4 = (float4*)out;
    for (int node = gwarp; node < NN; node += nw) {
        int s = g_off[node], e = g_off[node + 1];
        float4 acc = make_float4(0.f, 0.f, 0.f, 0.f);
        for (int i = s + par; i < e; i += 2) {
            int src = g_esrc[i];
            float4 v = g_y[(size_t)src * 16 + chunk];
            acc.x += v.x; acc.y += v.y; acc.z += v.z; acc.w += v.w;
        }
        acc.x += __shfl_down_sync(0xffffffffu, acc.x, 16);
        acc.y += __shfl_down_sync(0xffffffffu, acc.y, 16);
        acc.z += __shfl_down_sync(0xffffffffu, acc.z, 16);
        acc.w += __shfl_down_sync(0xffffffffu, acc.w, 16);
        if (par == 0) {
            float inv = g_inv[node];
            size_t oi = (size_t)node * 16 + chunk;
            float4 o = out4[oi];
            float4 b = *(const float4*)&b2[chunk * 4];
            out4[oi] = make_float4(o.x + acc.x * inv + b.x,
                                   o.y + acc.y * inv + b.y,
                                   o.z + acc.z * inv + b.z,
                                   o.w + acc.w * inv + b.w);
        }
    }
}

// -------------------------- layer 1: h = relu(mean1 @ W1l + x @ W1r + b1)
// 32-node tile; 256 thr = 8 node-grp(4) x 32 col-grp(4). FFMA2, features
// pre-packed in smem as broadcast (m,m)/(xv,xv) pairs. unroll 4 (reg budget).
__global__ void __launch_bounds__(256, 2)
layer1_kernel(const float* __restrict__ x,
              const float* __restrict__ W1l,
              const float* __restrict__ W1r,
              const float* __restrict__ b1) {
    extern __shared__ float smem[];
    float* sWl = smem;                         // DIN*DH = 32KB
    float* sWr = sWl + DIN * DH;               // 32KB
    float* sb1 = sWr + DIN * DH;               // 128
    ull*   sm  = (ull*)(sb1 + DH);             // 32*DIN packed (m,m)  = 16KB
    ull*   sxv = sm + 32 * DIN;                // 32*DIN packed (xv,xv)= 16KB

    int tid = threadIdx.x;
    for (int k = tid; k < DIN * DH; k += 256) { sWl[k] = W1l[k]; sWr[k] = W1r[k]; }
    if (tid < DH) sb1[tid] = b1[tid];

    const float* mean1 = (const float*)g_mean1;
    float* h = (float*)g_h4;
    int j0 = (tid & 31) * 4;   // 4 cols (2 packed pairs)
    int n0 = (tid >> 5) * 4;   // 4 nodes

    for (int tile = blockIdx.x; tile < NT1; tile += gridDim.x) {
        int base = tile * 32;
        __syncthreads();
        for (int idx = tid; idx < 32 * DIN; idx += 256) {
            int n = idx >> 6, k = idx & 63;
            int row = base + n;
            float m = 0.f, xv = 0.f;
            if (row < NN) {
                m  = mean1[(size_t)row * DIN + k];
                xv = x[(size_t)row * DIN + k];
            }
            sm[idx]  = pk2(m, m);
            sxv[idx] = pk2(xv, xv);
        }
        __syncthreads();

        ull acc[4][2];
        {
            ull b01 = pk2(sb1[j0], sb1[j0 + 1]);
            ull b23 = pk2(sb1[j0 + 2], sb1[j0 + 3]);
            #pragma unroll
            for (int i = 0; i < 4; i++) { acc[i][0] = b01; acc[i][1] = b23; }
        }

        #pragma unroll 4
        for (int k = 0; k < DIN; k++) {
            ulonglong2 wl = *(const ulonglong2*)&sWl[k * DH + j0];  // 2 packed pairs
            ulonglong2 wr = *(const ulonglong2*)&sWr[k * DH + j0];
            #pragma unroll
            for (int i = 0; i < 4; i++) {
                ull pm  = sm[(n0 + i) * DIN + k];
                ull pxv = sxv[(n0 + i) * DIN + k];
                fma2(acc[i][0], pm, wl.x);
                fma2(acc[i][1], pm, wl.y);
                fma2(acc[i][0], pxv, wr.x);
                fma2(acc[i][1], pxv, wr.y);
            }
        }
        #pragma unroll
        for (int i = 0; i < 4; i++) {
            int row = base + n0 + i;
            if (row < NN) {
                float a0, a1, a2, a3;
                upk2(a0, a1, acc[i][0]);
                upk2(a2, a3, acc[i][1]);
                *(float4*)&h[(size_t)row * DH + j0] =
                    make_float4(fmaxf(a0, 0.f), fmaxf(a1, 0.f),
                                fmaxf(a2, 0.f), fmaxf(a3, 0.f));
            }
        }
    }
}

// ---------------- fused: y = h @ W2l ; out_partial = h @ W2r  (R6 shape)
// 64-node tile; 256 thr = 16 node-groups(4) x 16 col-groups(4). FFMA2 packed.
__global__ void __launch_bounds__(256, 2)
hmul_kernel(const float* __restrict__ W2l,
            const float* __restrict__ W2r,
            float* __restrict__ out) {
    extern __shared__ float smem[];
    float* sWl = smem;                  // DH*DOUT = 32KB
    float* sWr = sWl + DH * DOUT;       // 32KB
    float* sh  = sWr + DH * DOUT;       // 64*DH = 32KB

    int tid = threadIdx.x;
    for (int k = tid; k < DH * DOUT; k += 256) { sWl[k] = W2l[k]; sWr[k] = W2r[k]; }

    const float* h = (const float*)g_h4;
    int j0 = (tid & 15) * 4;
    int n0 = (tid >> 4) * 4;

    for (int tile = blockIdx.x; tile < NTH; tile += gridDim.x) {
        int base = tile * 64;
        __syncthreads();
        for (int idx = tid; idx < 64 * DH; idx += 256) {
            int row = base + (idx >> 7);
            sh[idx] = (row < NN) ? h[(size_t)row * DH + (idx & 127)] : 0.f;
        }
        __syncthreads();

        ull ay[4][2], ao[4][2];
        #pragma unroll
        for (int i = 0; i < 4; i++) {
            ay[i][0] = 0ull; ay[i][1] = 0ull;
            ao[i][0] = 0ull; ao[i][1] = 0ull;
        }

        #pragma unroll 4
        for (int k = 0; k < DH; k++) {
            ulonglong2 wl = *(const ulonglong2*)&sWl[k * DOUT + j0];
            ulonglong2 wr = *(const ulonglong2*)&sWr[k * DOUT + j0];
            #pragma unroll
            for (int i = 0; i < 4; i++) {
                float f = sh[(n0 + i) * DH + k];
                ull pf = pk2(f, f);
                fma2(ay[i][0], pf, wl.x);
                fma2(ay[i][1], pf, wl.y);
                fma2(ao[i][0], pf, wr.x);
                fma2(ao[i][1], pf, wr.y);
            }
        }
        #pragma unroll
        for (int i = 0; i < 4; i++) {
            int row = base + n0 + i;
            if (row < NN) {
                float y0, y1, y2, y3, o0, o1, o2, o3;
                upk2(y0, y1, ay[i][0]); upk2(y2, y3, ay[i][1]);
                upk2(o0, o1, ao[i][0]); upk2(o2, o3, ao[i][1]);
                g_y[(size_t)row * 16 + (j0 >> 2)] = make_float4(y0, y1, y2, y3);
                *(float4*)&out[(size_t)row * DOUT + j0] = make_float4(o0, o1, o2, o3);
            }
        }
    }
}

// ---------------------------------------------------------------------------
extern "C" void kernel_launch(void* const* d_in, const int* in_sizes, int n_in,
                              void* d_out, int out_size) {
    const float* x   = (const float*)d_in[0];
    const float* W1l = (const float*)d_in[1];
    const float* W1r = (const float*)d_in[2];
    const float* b1  = (const float*)d_in[3];
    const float* W2l = (const float*)d_in[4];
    const float* W2r = (const float*)d_in[5];
    const float* b2  = (const float*)d_in[6];
    const int*   ei  = (const int*)d_in[7];
    float* out = (float*)d_out;

    const int L1_SMEM = (2 * DIN * DH + DH) * 4 + 2 * 32 * DIN * 8;   // 96.5 KB
    const int HM_SMEM = (2 * DH * DOUT + 64 * DH) * 4;                // 96 KB
    cudaFuncSetAttribute(layer1_kernel, cudaFuncAttributeMaxDynamicSharedMemorySize, L1_SMEM);
    cudaFuncSetAttribute(hmul_kernel,   cudaFuncAttributeMaxDynamicSharedMemorySize, HM_SMEM);

    detect_zero_kernel<<<(NN + 1023) / 1024, 1024>>>(ei);
    convert_kernel<<<(EE + 255) / 256, 256>>>(ei);
    scan1_kernel<<<NB_SCAN, 256>>>();
    scan3_kernel<<<NB_SCAN, 256>>>();
    place_kernel<<<(EE + 255) / 256, 256>>>();
    agg1_kernel<<<592, 256>>>(x);
    layer1_kernel<<<296, 256, L1_SMEM>>>(x, W1l, W1r, b1);
    hmul_kernel<<<296, 256, HM_SMEM>>>(W2l, W2r, out);
    agg2_kernel<<<592, 256>>>(b2, out);
}

// round 11
// speedup vs baseline: 1.1420x; 1.1420x over previous
#include <cuda_runtime.h>
#include <cuda_bf16.h>
#include <cstdint>

#define NN   100000
#define EE   1000000
#define DIN  64
#define DH   128
#define DOUT 64
#define NB_SCAN 391                     // ceil(NN/256)
#define NT1 ((NN + 31) / 32)            // layer1 tiles of 32 nodes
#define NTH ((NN + 63) / 64)            // hmul tiles of 64 nodes

typedef unsigned long long ull;

// ----- device scratch (no allocation allowed) -----
__device__ int    g_is64;
__device__ int    g_cnti[NN];
__device__ int    g_bsum[NB_SCAN];
__device__ int    g_off[NN + 1];
__device__ int    g_cur[NN];
__device__ float  g_inv[NN];
__device__ int    g_src[EE];
__device__ int    g_dst[EE];
__device__ int    g_esrc[EE];                      // src sorted by dst bucket
__device__ float4 g_mean1[(size_t)NN * (DIN / 4)];
__device__ float4 g_h4[(size_t)NN * (DH / 4)];
__device__ float4 g_y[(size_t)NN * (DOUT / 4)];

// ---- packed f32x2 helpers (Blackwell FFMA2 — ptxas never emits from C++) ----
__device__ __forceinline__ ull pk2(float a, float b) {
    ull r; asm("mov.b64 %0, {%1, %2};" : "=l"(r) : "f"(a), "f"(b)); return r;
}
__device__ __forceinline__ void upk2(float& a, float& b, ull v) {
    asm("mov.b64 {%0, %1}, %2;" : "=f"(a), "=f"(b) : "l"(v));
}
__device__ __forceinline__ void fma2(ull& d, ull a, ull b) {
    asm("fma.rn.f32x2 %0, %1, %2, %0;" : "+l"(d) : "l"(a), "l"(b));
}

// ------------------- detect edge_index storage width + zero degree histogram
__global__ void detect_zero_kernel(const int* __restrict__ ei) {
    int i = blockIdx.x * blockDim.x + threadIdx.x;
    if (i < NN) g_cnti[i] = 0;
    if (blockIdx.x == 0) {
        __shared__ int any_nonzero;
        if (threadIdx.x == 0) any_nonzero = 0;
        __syncthreads();
        int w = 1 + 2 * threadIdx.x;            // odd words 1..2047
        if (w < 2048 && ei[w] != 0) atomicExch(&any_nonzero, 1);
        __syncthreads();
        if (threadIdx.x == 0) g_is64 = any_nonzero ? 0 : 1;
    }
}

// --------------------------------- convert indices to int32 + degree histogram
__global__ void convert_kernel(const int* __restrict__ ei) {
    int e = blockIdx.x * blockDim.x + threadIdx.x;
    if (e >= EE) return;
    int is64 = g_is64;
    int s = is64 ? ei[2 * e] : ei[e];
    int d = is64 ? ei[2 * (EE + e)] : ei[EE + e];
    s = min(max(s, 0), NN - 1);
    d = min(max(d, 0), NN - 1);
    g_src[e] = s;
    g_dst[e] = d;
    atomicAdd(&g_cnti[d], 1);
}

// ------------------------------------------------------- 2-phase scan
__global__ void scan1_kernel() {
    __shared__ int s[256];
    int i = blockIdx.x * 256 + threadIdx.x;
    s[threadIdx.x] = (i < NN) ? g_cnti[i] : 0;
    __syncthreads();
    for (int d = 128; d > 0; d >>= 1) {
        if (threadIdx.x < d) s[threadIdx.x] += s[threadIdx.x + d];
        __syncthreads();
    }
    if (threadIdx.x == 0) g_bsum[blockIdx.x] = s[0];
}

// scan3: per-element offsets; block offset computed by reducing g_bsum[0..b)
__global__ void scan3_kernel() {
    __shared__ int s[256];
    __shared__ int sboff[256];
    int t = threadIdx.x;
    int part = 0;
    for (int k = t; k < blockIdx.x; k += 256) part += g_bsum[k];
    sboff[t] = part;
    __syncthreads();
    for (int d = 128; d > 0; d >>= 1) {
        if (t < d) sboff[t] += sboff[t + d];
        __syncthreads();
    }
    int block_off = sboff[0];

    int i = blockIdx.x * 256 + t;
    int c = (i < NN) ? g_cnti[i] : 0;
    s[t] = c;
    __syncthreads();
    for (int d = 1; d < 256; d <<= 1) {
        int v = (t >= d) ? s[t - d] : 0;
        __syncthreads();
        s[t] += v;
        __syncthreads();
    }
    if (i < NN) {
        int off = block_off + s[t] - c;
        g_off[i] = off;
        g_cur[i] = off;
        g_inv[i] = 1.0f / fmaxf((float)c, 1.0f);
    }
    if (i == 0) g_off[NN] = EE;
}

// -------------------------------------------------- bucket-place src by dst
__global__ void place_kernel() {
    int e = blockIdx.x * blockDim.x + threadIdx.x;
    if (e >= EE) return;
    int pos = atomicAdd(&g_cur[g_dst[e]], 1);
    g_esrc[pos] = g_src[e];
}

// ----------------------------------- gather-aggregate: mean1 = mean x[nbrs]
__global__ void __launch_bounds__(256)
agg1_kernel(const float* __restrict__ x) {
    int gwarp = (blockIdx.x * 256 + threadIdx.x) >> 5;
    int lane = threadIdx.x & 31;
    int nw = (gridDim.x * 256) >> 5;
    int chunk = lane & 15, par = lane >> 4;
    const float4* x4 = (const float4*)x;
    for (int node = gwarp; node < NN; node += nw) {
        int s = g_off[node], e = g_off[node + 1];
        float4 acc = make_float4(0.f, 0.f, 0.f, 0.f);
        for (int i = s + par; i < e; i += 2) {
            int src = g_esrc[i];
            float4 v = x4[(size_t)src * 16 + chunk];
            acc.x += v.x; acc.y += v.y; acc.z += v.z; acc.w += v.w;
        }
        acc.x += __shfl_down_sync(0xffffffffu, acc.x, 16);
        acc.y += __shfl_down_sync(0xffffffffu, acc.y, 16);
        acc.z += __shfl_down_sync(0xffffffffu, acc.z, 16);
        acc.w += __shfl_down_sync(0xffffffffu, acc.w, 16);
        if (par == 0) {
            float inv = g_inv[node];
            g_mean1[(size_t)node * 16 + chunk] =
                make_float4(acc.x * inv, acc.y * inv, acc.z * inv, acc.w * inv);
        }
    }
}

// --------------- gather-aggregate 2 FUSED: out += mean y[nbrs] + b2
__global__ void __launch_bounds__(256)
agg2_kernel(const float* __restrict__ b2, float* __restrict__ out) {
    int gwarp = (blockIdx.x * 256 + threadIdx.x) >> 5;
    int lane = threadIdx.x & 31;
    int nw = (gridDim.x * 256) >> 5;
    int chunk = lane & 15, par = lane >> 4;
    float4* out4 = (float4*)out;
    for (int node = gwarp; node < NN; node += nw) {
        int s = g_off[node], e = g_off[node + 1];
        float4 acc = make_float4(0.f, 0.f, 0.f, 0.f);
        for (int i = s + par; i < e; i += 2) {
            int src = g_esrc[i];
            float4 v = g_y[(size_t)src * 16 + chunk];
            acc.x += v.x; acc.y += v.y; acc.z += v.z; acc.w += v.w;
        }
        acc.x += __shfl_down_sync(0xffffffffu, acc.x, 16);
        acc.y += __shfl_down_sync(0xffffffffu, acc.y, 16);
        acc.z += __shfl_down_sync(0xffffffffu, acc.z, 16);
        acc.w += __shfl_down_sync(0xffffffffu, acc.w, 16);
        if (par == 0) {
            float inv = g_inv[node];
            size_t oi = (size_t)node * 16 + chunk;
            float4 o = out4[oi];
            float4 b = *(const float4*)&b2[chunk * 4];
            out4[oi] = make_float4(o.x + acc.x * inv + b.x,
                                   o.y + acc.y * inv + b.y,
                                   o.z + acc.z * inv + b.z,
                                   o.w + acc.w * inv + b.w);
        }
    }
}

// -------------------------- layer 1: h = relu(mean1 @ W1l + x @ W1r + b1)
// R6 shape: 32-node tile; 256 thr = 8 node-grp(4) x 32 col-grp(4). FFMA2.
__global__ void __launch_bounds__(256, 2)
layer1_kernel(const float* __restrict__ x,
              const float* __restrict__ W1l,
              const float* __restrict__ W1r,
              const float* __restrict__ b1) {
    extern __shared__ float smem[];
    float*  sWl   = smem;                        // DIN*DH = 32KB
    float*  sWr   = sWl + DIN * DH;              // 32KB
    float*  sb1   = sWr + DIN * DH;              // 128
    float2* sfeat = (float2*)(sb1 + DH);         // 32*DIN float2 = 16KB

    int tid = threadIdx.x;
    for (int k = tid; k < DIN * DH; k += 256) { sWl[k] = W1l[k]; sWr[k] = W1r[k]; }
    if (tid < DH) sb1[tid] = b1[tid];

    const float* mean1 = (const float*)g_mean1;
    float* h = (float*)g_h4;
    int j0 = (tid & 31) * 4;   // 4 cols (2 packed pairs)
    int n0 = (tid >> 5) * 4;   // 4 nodes

    for (int tile = blockIdx.x; tile < NT1; tile += gridDim.x) {
        int base = tile * 32;
        __syncthreads();
        for (int idx = tid; idx < 32 * DIN; idx += 256) {
            int n = idx >> 6, k = idx & 63;
            int row = base + n;
            float m = 0.f, xv = 0.f;
            if (row < NN) {
                m  = mean1[(size_t)row * DIN + k];
                xv = x[(size_t)row * DIN + k];
            }
            sfeat[n * DIN + k] = make_float2(m, xv);
        }
        __syncthreads();

        ull acc[4][2];
        {
            ull b01 = pk2(sb1[j0], sb1[j0 + 1]);
            ull b23 = pk2(sb1[j0 + 2], sb1[j0 + 3]);
            #pragma unroll
            for (int i = 0; i < 4; i++) { acc[i][0] = b01; acc[i][1] = b23; }
        }

        #pragma unroll 8
        for (int k = 0; k < DIN; k++) {
            ulonglong2 wl = *(const ulonglong2*)&sWl[k * DH + j0];  // 2 packed col-pairs
            ulonglong2 wr = *(const ulonglong2*)&sWr[k * DH + j0];
            #pragma unroll
            for (int i = 0; i < 4; i++) {
                float2 f = sfeat[(n0 + i) * DIN + k];
                ull pm  = pk2(f.x, f.x);
                ull pxv = pk2(f.y, f.y);
                fma2(acc[i][0], pm, wl.x);
                fma2(acc[i][1], pm, wl.y);
                fma2(acc[i][0], pxv, wr.x);
                fma2(acc[i][1], pxv, wr.y);
            }
        }
        #pragma unroll
        for (int i = 0; i < 4; i++) {
            int row = base + n0 + i;
            if (row < NN) {
                float a0, a1, a2, a3;
                upk2(a0, a1, acc[i][0]);
                upk2(a2, a3, acc[i][1]);
                *(float4*)&h[(size_t)row * DH + j0] =
                    make_float4(fmaxf(a0, 0.f), fmaxf(a1, 0.f),
                                fmaxf(a2, 0.f), fmaxf(a3, 0.f));
            }
        }
    }
}

// ---------------- fused: y = h @ W2l ; out_partial = h @ W2r  (R6 shape)
// 64-node tile; 256 thr = 16 node-groups(4) x 16 col-groups(4). FFMA2 packed.
__global__ void __launch_bounds__(256, 2)
hmul_kernel(const float* __restrict__ W2l,
            const float* __restrict__ W2r,
            float* __restrict__ out) {
    extern __shared__ float smem[];
    float* sWl = smem;                  // DH*DOUT = 32KB
    float* sWr = sWl + DH * DOUT;       // 32KB
    float* sh  = sWr + DH * DOUT;       // 64*DH = 32KB

    int tid = threadIdx.x;
    for (int k = tid; k < DH * DOUT; k += 256) { sWl[k] = W2l[k]; sWr[k] = W2r[k]; }

    const float* h = (const float*)g_h4;
    int j0 = (tid & 15) * 4;
    int n0 = (tid >> 4) * 4;

    for (int tile = blockIdx.x; tile < NTH; tile += gridDim.x) {
        int base = tile * 64;
        __syncthreads();
        for (int idx = tid; idx < 64 * DH; idx += 256) {
            int row = base + (idx >> 7);
            sh[idx] = (row < NN) ? h[(size_t)row * DH + (idx & 127)] : 0.f;
        }
        __syncthreads();

        ull ay[4][2], ao[4][2];
        #pragma unroll
        for (int i = 0; i < 4; i++) {
            ay[i][0] = 0ull; ay[i][1] = 0ull;
            ao[i][0] = 0ull; ao[i][1] = 0ull;
        }

        #pragma unroll 4
        for (int k = 0; k < DH; k++) {
            ulonglong2 wl = *(const ulonglong2*)&sWl[k * DOUT + j0];
            ulonglong2 wr = *(const ulonglong2*)&sWr[k * DOUT + j0];
            #pragma unroll
            for (int i = 0; i < 4; i++) {
                float f = sh[(n0 + i) * DH + k];
                ull pf = pk2(f, f);
                fma2(ay[i][0], pf, wl.x);
                fma2(ay[i][1], pf, wl.y);
                fma2(ao[i][0], pf, wr.x);
                fma2(ao[i][1], pf, wr.y);
            }
        }
        #pragma unroll
        for (int i = 0; i < 4; i++) {
            int row = base + n0 + i;
            if (row < NN) {
                float y0, y1, y2, y3, o0, o1, o2, o3;
                upk2(y0, y1, ay[i][0]); upk2(y2, y3, ay[i][1]);
                upk2(o0, o1, ao[i][0]); upk2(o2, o3, ao[i][1]);
                g_y[(size_t)row * 16 + (j0 >> 2)] = make_float4(y0, y1, y2, y3);
                *(float4*)&out[(size_t)row * DOUT + j0] = make_float4(o0, o1, o2, o3);
            }
        }
    }
}

// ---------------------------------------------------------------------------
extern "C" void kernel_launch(void* const* d_in, const int* in_sizes, int n_in,
                              void* d_out, int out_size) {
    const float* x   = (const float*)d_in[0];
    const float* W1l = (const float*)d_in[1];
    const float* W1r = (const float*)d_in[2];
    const float* b1  = (const float*)d_in[3];
    const float* W2l = (const float*)d_in[4];
    const float* W2r = (const float*)d_in[5];
    const float* b2  = (const float*)d_in[6];
    const int*   ei  = (const int*)d_in[7];
    float* out = (float*)d_out;

    const int L1_SMEM = (2 * DIN * DH + DH + 2 * 32 * DIN) * 4;   // 80.5 KB
    const int HM_SMEM = (2 * DH * DOUT + 64 * DH) * 4;            // 96 KB
    cudaFuncSetAttribute(layer1_kernel, cudaFuncAttributeMaxDynamicSharedMemorySize, L1_SMEM);
    cudaFuncSetAttribute(hmul_kernel,   cudaFuncAttributeMaxDynamicSharedMemorySize, HM_SMEM);

    detect_zero_kernel<<<(NN + 1023) / 1024, 1024>>>(ei);
    convert_kernel<<<(EE + 255) / 256, 256>>>(ei);
    scan1_kernel<<<NB_SCAN, 256>>>();
    scan3_kernel<<<NB_SCAN, 256>>>();
    place_kernel<<<(EE + 255) / 256, 256>>>();
    agg1_kernel<<<1184, 256>>>(x);
    layer1_kernel<<<296, 256, L1_SMEM>>>(x, W1l, W1r, b1);
    hmul_kernel<<<296, 256, HM_SMEM>>>(W2l, W2r, out);
    agg2_kernel<<<1184, 256>>>(b2, out);
}